// round 6
// baseline (speedup 1.0000x reference)
#include <cuda_runtime.h>
#include <cstdint>

#define M_DIM 512
#define K_DIM 256
#define O_DIM 256
#define KSPLIT 4
#define BK 64
#define RBLK 128          /* reduce blocks */

#define BIGF  12582912.0f          /* 1.5 * 2^23 */
#define BIGU  0x4B400000u
#define THETA 0.0009765625f        /* 2^-10 */
#define EPSB  0.000244140625f      /* 2^-12 */

// ---------------- device scratch (no allocations allowed) ----------------
__device__ float2 g_bmax2[RBLK];               // per-block (max|x|, max(|W|,|b|))
__device__ float g_af[M_DIM * K_DIM];          // float(aa) + 2^-10, row-major [m][k]
__device__ float g_us[O_DIM * K_DIM];          // bb/32 (- 2^-12 if bb<0), row-major [o][k]
__device__ int2  g_oc[O_DIM];                  // {N_o = #neg(bb) in row o, cc_o}
__device__ float g_sn[2];                      // {sn1, sn2}
__device__ int   g_part[KSPLIT][M_DIM * O_DIM];

// ---------------- helpers ----------------
__device__ __forceinline__ float san(float v) {
    if (isnan(v)) return 0.0f;
    if (isinf(v)) return 1.0f;
    return v;
}

// sn = 2^floor(log2(floor(32/mx))); argument of log2 is a positive integer.
__device__ __forceinline__ float calc_sn(float mx) {
    if (mx == 0.0f) mx = 1.0f;
    float r = floorf(32.0f / mx);
    return ldexpf(1.0f, ilogbf(r));
}

// block-level max reduce of (mx, md) over 256 threads; result valid in ALL threads
__device__ __forceinline__ float2 block_max2(float mx, float md) {
    __shared__ float2 s_red[8];
    __shared__ float2 s_out;
    #pragma unroll
    for (int off = 16; off; off >>= 1) {
        mx = fmaxf(mx, __shfl_xor_sync(0xFFFFFFFFu, mx, off));
        md = fmaxf(md, __shfl_xor_sync(0xFFFFFFFFu, md, off));
    }
    if ((threadIdx.x & 31) == 0) s_red[threadIdx.x >> 5] = make_float2(mx, md);
    __syncthreads();
    if (threadIdx.x == 0) {
        float2 r = s_red[0];
        #pragma unroll
        for (int w = 1; w < 8; w++) {
            r.x = fmaxf(r.x, s_red[w].x);
            r.y = fmaxf(r.y, s_red[w].y);
        }
        s_out = r;
    }
    __syncthreads();
    return s_out;
}

// ---------------- pass 1: per-block maxima (no atomics, no reset) ----------------
__global__ __launch_bounds__(256) void reduce_kernel(const float* __restrict__ x,
                                                     const float* __restrict__ W,
                                                     const float* __restrict__ b) {
    float mx = 0.0f, md = 0.0f;
    int t = blockIdx.x * 256 + threadIdx.x;
    const int stride = RBLK * 256;
    for (int i = t; i < M_DIM * K_DIM; i += stride) mx = fmaxf(mx, fabsf(san(x[i])));
    for (int i = t; i < O_DIM * K_DIM; i += stride) md = fmaxf(md, fabsf(san(W[i])));
    md = fmaxf(md, fabsf(san(b[threadIdx.x])));   // 256 threads cover b exactly
    float2 r = block_max2(mx, md);
    if (threadIdx.x == 0) g_bmax2[blockIdx.x] = r;
}

// ---------------- pass 2: quantize (row-major, coalesced) + per-o metadata ------
__global__ __launch_bounds__(256) void quant_kernel(const float* __restrict__ x,
                                                    const float* __restrict__ W,
                                                    const float* __restrict__ b) {
    __shared__ int s_neg[8];

    // prologue: final max over 128 block results
    float mx = 0.0f, md = 0.0f;
    if (threadIdx.x < RBLK) {
        float2 v = g_bmax2[threadIdx.x];
        mx = v.x; md = v.y;
    }
    float2 r = block_max2(mx, md);
    float sn2 = calc_sn(r.x);
    float sn1 = calc_sn(r.y);

    int i = blockIdx.x * 256 + threadIdx.x;   // grid covers M*K
    // x -> af' = float(trunc(x*sn2)) + 2^-10
    g_af[i] = (float)(int)(san(x[i]) * sn2) + THETA;

    // blocks 0..255 each cover exactly one o-row of W (256 consecutive k)
    if (i < O_DIM * K_DIM) {
        int bb = (int)(san(W[i]) * sn1);
        float us = (float)bb * (1.0f / 32.0f);
        if (bb < 0) us -= EPSB;
        g_us[i] = us;
        unsigned ball = __ballot_sync(0xFFFFFFFFu, bb < 0);
        if ((threadIdx.x & 31) == 0) s_neg[threadIdx.x >> 5] = __popc(ball);
        __syncthreads();
        if (threadIdx.x == 0) {
            int N = 0;
            #pragma unroll
            for (int w = 0; w < 8; w++) N += s_neg[w];
            g_oc[blockIdx.x] = make_int2(N, (int)(san(b[blockIdx.x]) * sn1));
        }
    }
    if (i == 0) { g_sn[0] = sn1; g_sn[1] = sn2; }
}

// ---------------- pass 3: LUT-GEMM, 2 instr/MAC (FFMA.RD + IADD3) ----------------
// grid (8 o-blk, 16 m-blk, KSPLIT); tile 32m x 32o x 64k; 256 threads, 2x2/thread.
__global__ __launch_bounds__(256) void gemm_kernel() {
    __shared__ float s_a[BK][34];   // [k][m], pad 34 keeps float2 aligned, <=4-way STS
    __shared__ float s_u[BK][34];   // [k][o]

    int m0 = blockIdx.y * 32;
    int o0 = blockIdx.x * 32;
    int kc = blockIdx.z * BK;

    // stage: coalesced LDG.128 row-major, transposed STS into smem
    int mm = threadIdx.x >> 3;
    int kg = (threadIdx.x & 7) << 3;
    {
        const float4* pa = (const float4*)&g_af[(m0 + mm) * K_DIM + kc + kg];
        const float4* pu = (const float4*)&g_us[(o0 + mm) * K_DIM + kc + kg];
        float4 a0 = pa[0], a1 = pa[1];
        float4 u0 = pu[0], u1 = pu[1];
        s_a[kg + 0][mm] = a0.x; s_a[kg + 1][mm] = a0.y;
        s_a[kg + 2][mm] = a0.z; s_a[kg + 3][mm] = a0.w;
        s_a[kg + 4][mm] = a1.x; s_a[kg + 5][mm] = a1.y;
        s_a[kg + 6][mm] = a1.z; s_a[kg + 7][mm] = a1.w;
        s_u[kg + 0][mm] = u0.x; s_u[kg + 1][mm] = u0.y;
        s_u[kg + 2][mm] = u0.z; s_u[kg + 3][mm] = u0.w;
        s_u[kg + 4][mm] = u1.x; s_u[kg + 5][mm] = u1.y;
        s_u[kg + 6][mm] = u1.z; s_u[kg + 7][mm] = u1.w;
    }
    __syncthreads();

    int tx = threadIdx.x & 15;      // o
    int ty = threadIdx.x >> 4;      // m

    unsigned acc00 = 0, acc01 = 0, acc10 = 0, acc11 = 0;

    #pragma unroll 16
    for (int k = 0; k < BK; k++) {
        float2 av = *reinterpret_cast<const float2*>(&s_a[k][2 * ty]);
        float2 uv = *reinterpret_cast<const float2*>(&s_u[k][2 * tx]);
        acc00 += __float_as_uint(__fmaf_rd(av.x, uv.x, BIGF));
        acc01 += __float_as_uint(__fmaf_rd(av.x, uv.y, BIGF));
        acc10 += __float_as_uint(__fmaf_rd(av.y, uv.x, BIGF));
        acc11 += __float_as_uint(__fmaf_rd(av.y, uv.y, BIGF));
    }

    const unsigned C = (unsigned)(64u * BIGU);   // mod 2^32 wraparound
    int m = m0 + 2 * ty;
    int o = o0 + 2 * tx;
    int* __restrict__ p = g_part[blockIdx.z];
    *reinterpret_cast<int2*>(&p[m * O_DIM + o]) =
        make_int2((int)(acc00 - C), (int)(acc01 - C));
    *reinterpret_cast<int2*>(&p[(m + 1) * O_DIM + o]) =
        make_int2((int)(acc10 - C), (int)(acc11 - C));
}

// ---------------- pass 4: 1 output/thread, fully coalesced ----------------------
__global__ __launch_bounds__(256) void epilogue_kernel(float* __restrict__ out) {
    int idx = blockIdx.x * 256 + threadIdx.x;   // grid covers M*O exactly
    float sn1 = g_sn[0], sn2 = g_sn[1];
    int2 oc = g_oc[idx & (O_DIM - 1)];
    int x9 = g_part[0][idx] + g_part[1][idx] + g_part[2][idx] + g_part[3][idx] + oc.x;
    // d = trunc(x9/sn2) + cc ; out = d/sn1 (exact pow-2 ops, trunc = C cast)
    out[idx] = (float)((int)((float)x9 / sn2) + oc.y) / sn1;
}

// ---------------- launch ----------------
extern "C" void kernel_launch(void* const* d_in, const int* in_sizes, int n_in,
                              void* d_out, int out_size) {
    (void)in_sizes; (void)n_in; (void)out_size;
    const float* x = (const float*)d_in[0];
    const float* W = (const float*)d_in[1];
    const float* b = (const float*)d_in[2];
    // d_in[3] (lut) unused: lut[i][j] == floor(i*j/32), reproduced exactly by
    // the FFMA.RD magic-floor + raw-bits accumulation.

    reduce_kernel<<<RBLK, 256>>>(x, W, b);
    quant_kernel<<<(M_DIM * K_DIM) / 256, 256>>>(x, W, b);
    dim3 grid(O_DIM / 32, M_DIM / 32, KSPLIT);
    gemm_kernel<<<grid, 256>>>();
    epilogue_kernel<<<(M_DIM * O_DIM) / 256, 256>>>((float*)d_out);
}

// round 7
// speedup vs baseline: 1.5254x; 1.5254x over previous
#include <cuda_runtime.h>
#include <cstdint>

#define M_DIM 512
#define K_DIM 256
#define O_DIM 256
#define BK 64
#define RBLK 128          /* reduce blocks */

#define BIGF  12582912.0f          /* 1.5 * 2^23 */
#define BIGU  0x4B400000u
#define THETA 0.0009765625f        /* 2^-10 */
#define EPSB  0.000244140625f      /* 2^-12 */

// ---------------- device scratch (no allocations allowed) ----------------
__device__ float2 g_bmax2[RBLK];   // per-block (max|x|, max(|W|,|b|))

// ---------------- helpers ----------------
__device__ __forceinline__ float san(float v) {
    if (isnan(v)) return 0.0f;
    if (isinf(v)) return 1.0f;
    return v;
}

// sn = 2^floor(log2(floor(32/mx))); argument of log2 is a positive integer.
__device__ __forceinline__ float calc_sn(float mx) {
    if (mx == 0.0f) mx = 1.0f;
    float r = floorf(32.0f / mx);
    return ldexpf(1.0f, ilogbf(r));
}

// block-level max reduce of (mx, md) over 256 threads; result valid in ALL threads
__device__ __forceinline__ float2 block_max2(float mx, float md) {
    __shared__ float2 s_red[8];
    __shared__ float2 s_out;
    #pragma unroll
    for (int off = 16; off; off >>= 1) {
        mx = fmaxf(mx, __shfl_xor_sync(0xFFFFFFFFu, mx, off));
        md = fmaxf(md, __shfl_xor_sync(0xFFFFFFFFu, md, off));
    }
    if ((threadIdx.x & 31) == 0) s_red[threadIdx.x >> 5] = make_float2(mx, md);
    __syncthreads();
    if (threadIdx.x == 0) {
        float2 r = s_red[0];
        #pragma unroll
        for (int w = 1; w < 8; w++) {
            r.x = fmaxf(r.x, s_red[w].x);
            r.y = fmaxf(r.y, s_red[w].y);
        }
        s_out = r;
    }
    __syncthreads();
    return s_out;
}

// ---------------- pass 1: per-block maxima (no atomics, no reset) ----------------
__global__ __launch_bounds__(256) void reduce_kernel(const float* __restrict__ x,
                                                     const float* __restrict__ W,
                                                     const float* __restrict__ b) {
    float mx = 0.0f, md = 0.0f;
    int t = blockIdx.x * 256 + threadIdx.x;
    const int stride = RBLK * 256;
    for (int i = t; i < M_DIM * K_DIM; i += stride) mx = fmaxf(mx, fabsf(san(x[i])));
    for (int i = t; i < O_DIM * K_DIM; i += stride) md = fmaxf(md, fabsf(san(W[i])));
    md = fmaxf(md, fabsf(san(b[threadIdx.x])));   // 256 threads cover b exactly
    float2 r = block_max2(mx, md);
    if (threadIdx.x == 0) g_bmax2[blockIdx.x] = r;
}

// ---------------- pass 2: fused quantize + LUT-GEMM + epilogue ----------------
// grid (8 o-blk, 16 m-blk) = 128 blocks; tile 32m x 32o, full K=256 in 4 smem
// stages; 256 threads, 2x2 outputs/thread. 2 instr/MAC (FFMA.RD + IADD3).
__global__ __launch_bounds__(256) void fused_kernel(const float* __restrict__ x,
                                                    const float* __restrict__ W,
                                                    const float* __restrict__ b,
                                                    float* __restrict__ out) {
    __shared__ float s_a[BK][34];   // [k][m], pad keeps float2 aligned, conflict-free
    __shared__ float s_u[BK][34];   // [k][o]
    __shared__ int   s_neg[32];     // per local-o count of bb<0 over full K

    // prologue: finalize global maxima -> sn1, sn2 (all threads)
    float mx = 0.0f, md = 0.0f;
    if (threadIdx.x < RBLK) {
        float2 v = g_bmax2[threadIdx.x];
        mx = v.x; md = v.y;
    }
    float2 r = block_max2(mx, md);
    float sn2 = calc_sn(r.x);
    float sn1 = calc_sn(r.y);

    int m0 = blockIdx.y * 32;
    int o0 = blockIdx.x * 32;
    int mm = threadIdx.x >> 3;          // staging row (m for x, o for W)
    int kg = (threadIdx.x & 7) << 3;    // staging k-offset (8 floats)
    int tx = threadIdx.x & 15;          // output o
    int ty = threadIdx.x >> 4;          // output m

    unsigned acc00 = 0, acc01 = 0, acc10 = 0, acc11 = 0;
    int negcnt = 0;

    for (int kc = 0; kc < K_DIM; kc += BK) {
        // stage + on-the-fly quantize (coalesced LDG.128, transposed STS)
        const float4* pa = (const float4*)&x[(m0 + mm) * K_DIM + kc + kg];
        const float4* pw = (const float4*)&W[(o0 + mm) * K_DIM + kc + kg];
        float4 a0 = pa[0], a1 = pa[1];
        float4 w0 = pw[0], w1 = pw[1];
        float av[8] = {a0.x, a0.y, a0.z, a0.w, a1.x, a1.y, a1.z, a1.w};
        float wv[8] = {w0.x, w0.y, w0.z, w0.w, w1.x, w1.y, w1.z, w1.w};
        #pragma unroll
        for (int j = 0; j < 8; j++) {
            // af' = float(trunc(x*sn2)) + 2^-10
            s_a[kg + j][mm] = (float)(int)(san(av[j]) * sn2) + THETA;
            // us' = bb/32 (- 2^-12 if bb<0); count negatives for bias fix
            int bb = (int)(san(wv[j]) * sn1);
            float us = (float)bb * (1.0f / 32.0f);
            if (bb < 0) { us -= EPSB; negcnt++; }
            s_u[kg + j][mm] = us;
        }
        __syncthreads();

        #pragma unroll 16
        for (int k = 0; k < BK; k++) {
            float2 a2 = *reinterpret_cast<const float2*>(&s_a[k][2 * ty]);
            float2 u2 = *reinterpret_cast<const float2*>(&s_u[k][2 * tx]);
            acc00 += __float_as_uint(__fmaf_rd(a2.x, u2.x, BIGF));
            acc01 += __float_as_uint(__fmaf_rd(a2.x, u2.y, BIGF));
            acc10 += __float_as_uint(__fmaf_rd(a2.y, u2.x, BIGF));
            acc11 += __float_as_uint(__fmaf_rd(a2.y, u2.y, BIGF));
        }
        __syncthreads();
    }

    // per-o negative count: sum over the 8 staging threads sharing o-row mm
    // (they are 8 consecutive lanes within one warp)
    #pragma unroll
    for (int off = 1; off < 8; off <<= 1)
        negcnt += __shfl_xor_sync(0xFFFFFFFFu, negcnt, off);
    if ((threadIdx.x & 7) == 0) s_neg[mm] = negcnt;
    __syncthreads();

    // epilogue: x9 = (acc - K*BIGU mod 2^32) + N_o ; d = trunc(x9/sn2) + cc ;
    // out = d/sn1  (exact pow-2 ops, trunc = C cast)
    const unsigned C = (unsigned)((unsigned)K_DIM * BIGU);
    int o = o0 + 2 * tx;
    int m = m0 + 2 * ty;
    int n0 = s_neg[2 * tx], n1 = s_neg[2 * tx + 1];
    int c0 = (int)(san(b[o])     * sn1);
    int c1 = (int)(san(b[o + 1]) * sn1);

    int x900 = (int)(acc00 - C) + n0;
    int x901 = (int)(acc01 - C) + n1;
    int x910 = (int)(acc10 - C) + n0;
    int x911 = (int)(acc11 - C) + n1;

    float2 r0, r1;
    r0.x = (float)((int)((float)x900 / sn2) + c0) / sn1;
    r0.y = (float)((int)((float)x901 / sn2) + c1) / sn1;
    r1.x = (float)((int)((float)x910 / sn2) + c0) / sn1;
    r1.y = (float)((int)((float)x911 / sn2) + c1) / sn1;

    *reinterpret_cast<float2*>(&out[m * O_DIM + o])       = r0;
    *reinterpret_cast<float2*>(&out[(m + 1) * O_DIM + o]) = r1;
}

// ---------------- launch ----------------
extern "C" void kernel_launch(void* const* d_in, const int* in_sizes, int n_in,
                              void* d_out, int out_size) {
    (void)in_sizes; (void)n_in; (void)out_size;
    const float* x = (const float*)d_in[0];
    const float* W = (const float*)d_in[1];
    const float* b = (const float*)d_in[2];
    // d_in[3] (lut) unused: lut[i][j] == floor(i*j/32), reproduced exactly by
    // the FFMA.RD magic-floor + raw-bits accumulation.

    reduce_kernel<<<RBLK, 256>>>(x, W, b);
    dim3 grid(O_DIM / 32, M_DIM / 32);
    fused_kernel<<<grid, 256>>>(x, W, b, (float*)d_out);
}